// round 11
// baseline (speedup 1.0000x reference)
#include <cuda_runtime.h>

// YoloLoss: N=4096, S=14, B=2, NUM_CLS=20.
// Best-of-both: R9 1-cell fused body (measured-fastest main, 31.4us) +
// R10 tail (pre-scaled fire-and-forget REDs into d_out, graph memset node).
// NO gpu-scope fences anywhere (measured +15us L1-flush penalty R3/R5/R7).
// inputs: pred_tensor (N,S,S,30) f32, target_boxes (N,S,S,4) f32,
//         target_cls (N,S,S,20) f32, has_object_map (N,S,S) int32
// output: 5 f32 = (total, reg, contain_conf, no_obj, cls)

static constexpr int NSAMP = 4096;
static constexpr int S2    = 14 * 14;
static constexpr int NCELL = NSAMP * S2;   // 802816
static constexpr int CPB   = 128;          // cells (== threads) per block
static constexpr int NBLK  = NCELL / CPB;  // 6272

__global__ __launch_bounds__(CPB, 16) void yolo_k(
    const float* __restrict__ pred,
    const float* __restrict__ tbox,
    const float* __restrict__ tcls,
    const int* __restrict__ mask,
    float* __restrict__ out)
{
    // box channels only: stride 11 (odd -> conflict-free per-cell reads)
    __shared__ float sp[CPB * 11];      // 5632 B
    __shared__ float smask[CPB];
    __shared__ float red[CPB / 32][4];

    const int tid = threadIdx.x;
    const long base = (long)blockIdx.x * CPB;

    // mask first: the fused staging loop needs smask[] for cls terms
    smask[tid] = (mask[base + tid] != 0) ? 1.0f : 0.0f;
    __syncthreads();

    // --- fused staging: pred float2 stream; box pairs -> smem,
    //     cls pairs -> immediate (p - t)^2 * m accumulation.
    //     30 even => a pair never splits a cell; pairs never straddle ch=10.
    const float2* __restrict__ pg2 =
        reinterpret_cast<const float2*>(pred + base * 30);
    const float* __restrict__ cg = tcls + base * 20;
    float cls = 0.0f;
#pragma unroll
    for (int i = 0; i < 15; i++) {
        int idx2 = tid + i * CPB;       // 0..1919
        float2 v = pg2[idx2];
        int e    = idx2 * 2;
        int cell = e / 30;
        int ch   = e - cell * 30;       // even
        if (ch < 10) {
            sp[cell * 11 + ch]     = v.x;
            sp[cell * 11 + ch + 1] = v.y;
        } else {
            const float2 t =
                *reinterpret_cast<const float2*>(cg + cell * 20 + (ch - 10));
            float d0 = v.x - t.x, d1 = v.y - t.y;
            cls += (d0 * d0 + d1 * d1) * smask[cell];
        }
    }
    __syncthreads();

    // --- per-cell box terms ---
    const float4 tb = reinterpret_cast<const float4*>(tbox)[base + tid];
    const float  m  = smask[tid];
    const float* P  = &sp[tid * 11];

    float c0 = P[4], c1 = P[9];
    float noobj = (c0 * c0 + c1 * c1) * (1.0f - m);   // 0.5 applied pre-RED

    const float invS = 1.0f / 14.0f;
    float gx1 = tb.x * invS - 0.5f * tb.z, gx2 = tb.x * invS + 0.5f * tb.z;
    float gy1 = tb.y * invS - 0.5f * tb.w, gy2 = tb.y * invS + 0.5f * tb.w;
    float area_g = (gx2 - gx1) * (gy2 - gy1);

    float iou0, iou1;
#pragma unroll
    for (int b = 0; b < 2; b++) {
        float px = P[5 * b + 0], py = P[5 * b + 1];
        float pw = P[5 * b + 2], ph = P[5 * b + 3];
        float px1 = px * invS - 0.5f * pw, px2 = px * invS + 0.5f * pw;
        float py1 = py * invS - 0.5f * ph, py2 = py * invS + 0.5f * ph;
        float iw = fmaxf(fminf(px2, gx2) - fmaxf(px1, gx1), 0.0f);
        float ih = fmaxf(fminf(py2, gy2) - fmaxf(py1, gy1), 0.0f);
        float inter  = iw * ih;
        float area_p = (px2 - px1) * (py2 - py1);
        float v = inter / (area_p + area_g - inter);
        if (b == 0) iou0 = v; else iou1 = v;
    }
    // jnp.argmax keeps first max on ties -> strict '>' for box 1
    const int best = (iou1 > iou0) ? 1 : 0;
    const float bx = P[5 * best + 0], by = P[5 * best + 1];
    const float bw = P[5 * best + 2], bh = P[5 * best + 3];
    const float bc = P[5 * best + 4];

    float dx = bx - tb.x, dy = by - tb.y;
    float dw = sqrtf(bw) - sqrtf(tb.z);
    float dh = sqrtf(bh) - sqrtf(tb.w);
    float regp = (dx * dx + dy * dy + dw * dw + dh * dh) * m;
    float dc = bc - 1.0f;
    float contain = dc * dc * m;

    // --- reduction: warp shuffle -> smem -> 5 pre-scaled REDs into d_out ---
    float v0 = regp, v1 = contain, v2 = noobj, v3 = cls;
#pragma unroll
    for (int off = 16; off > 0; off >>= 1) {
        v0 += __shfl_xor_sync(0xffffffffu, v0, off);
        v1 += __shfl_xor_sync(0xffffffffu, v1, off);
        v2 += __shfl_xor_sync(0xffffffffu, v2, off);
        v3 += __shfl_xor_sync(0xffffffffu, v3, off);
    }
    const int warp = tid >> 5;
    if ((tid & 31) == 0) {
        red[warp][0] = v0; red[warp][1] = v1;
        red[warp][2] = v2; red[warp][3] = v3;
    }
    __syncthreads();
    if (tid < 5) {
        float s0 = red[0][0] + red[1][0] + red[2][0] + red[3][0]; // reg raw
        float s1 = red[0][1] + red[1][1] + red[2][1] + red[3][1]; // contain
        float s2 = red[0][2] + red[1][2] + red[2][2] + red[3][2]; // noobj raw
        float s3 = red[0][3] + red[1][3] + red[2][3] + red[3][3]; // cls
        const float invN = 1.0f / (float)NSAMP;
        float val;
        switch (tid) {
            case 0: val = (5.0f * s0 + s1 + 0.5f * s2 + s3) * invN; break;
            case 1: val = 5.0f * s0 * invN; break;
            case 2: val = s1 * invN; break;
            case 3: val = 0.5f * s2 * invN; break;
            default: val = s3 * invN; break;
        }
        atomicAdd(&out[tid], val);   // return unused -> RED, no ordering op
    }
}

extern "C" void kernel_launch(void* const* d_in, const int* in_sizes, int n_in,
                              void* d_out, int out_size)
{
    const float* pred = (const float*)d_in[0];
    const float* tbox = (const float*)d_in[1];
    const float* tcls = (const float*)d_in[2];
    const int*   mask = (const int*)d_in[3];
    float* out = (float*)d_out;

    // graph memset node: zero the 5 output floats each replay (REDs add onto it)
    cudaMemsetAsync(out, 0, 5 * sizeof(float), 0);
    yolo_k<<<NBLK, CPB>>>(pred, tbox, tcls, mask, out);
}